// round 6
// baseline (speedup 1.0000x reference)
#include <cuda_runtime.h>

#define EPS 1e-8f
#define NTHREADS 256
#define NBLOCKS 1184              // 148 SMs x 8 blocks/SM @32regs = exactly one wave
#define MAX_PARTIALS 4096

__device__ float g_partials[MAX_PARTIALS];
__device__ unsigned int g_done_count;   // zero-init; reset by last block each launch

__global__ __launch_bounds__(NTHREADS, 8) void cce_fused_kernel(
    const float* __restrict__ input,
    const float* __restrict__ target,
    long long n4,        // number of float4 elements
    float inv_b,
    float* __restrict__ out)
{
    const float4* __restrict__ in4 = (const float4*)input;
    const float4* __restrict__ tg4 = (const float4*)target;

    // balanced contiguous per-block partition: block b owns q + (b < r) rows
    const long long q = n4 / NBLOCKS;
    const long long r = n4 % NBLOCKS;
    const long long b = blockIdx.x;
    const long long start = b * q + (b < r ? b : r);
    const long long end   = start + q + (b < r ? 1 : 0);

    float acc0 = 0.0f, acc1 = 0.0f, acc2 = 0.0f, acc3 = 0.0f;

    #pragma unroll 2
    for (long long i = start + threadIdx.x; i < end; i += NTHREADS) {
        float4 a = __ldcs(&in4[i]);
        float4 t = __ldcs(&tg4[i]);
        acc0 += a.x * __logf(t.x + EPS);
        acc1 += a.y * __logf(t.y + EPS);
        acc2 += a.z * __logf(t.z + EPS);
        acc3 += a.w * __logf(t.w + EPS);
    }

    float acc = (acc0 + acc1) + (acc2 + acc3);

    // intra-block reduction (fp32)
    #pragma unroll
    for (int off = 16; off > 0; off >>= 1)
        acc += __shfl_xor_sync(0xFFFFFFFFu, acc, off);

    __shared__ float warp_sums[NTHREADS / 32];
    int lane = threadIdx.x & 31;
    int wid  = threadIdx.x >> 5;
    if (lane == 0) warp_sums[wid] = acc;
    __syncthreads();

    __shared__ bool is_last;
    if (threadIdx.x == 0) {
        float v = warp_sums[0];
        #pragma unroll
        for (int w = 1; w < NTHREADS / 32; w++) v += warp_sums[w];
        g_partials[blockIdx.x] = v;
        __threadfence();
        unsigned int prev = atomicAdd(&g_done_count, 1u);
        is_last = (prev == (unsigned int)(gridDim.x - 1));
        if (is_last) g_done_count = 0u;   // reset for next graph replay
    }
    __syncthreads();

    if (is_last) {
        // deterministic final sum in double (fixed read + reduction order)
        double dacc = 0.0;
        for (int i = threadIdx.x; i < NBLOCKS; i += NTHREADS)
            dacc += (double)g_partials[i];

        #pragma unroll
        for (int off = 16; off > 0; off >>= 1)
            dacc += __shfl_xor_sync(0xFFFFFFFFu, dacc, off);

        __shared__ double dwarp_sums[NTHREADS / 32];
        if (lane == 0) dwarp_sums[wid] = dacc;
        __syncthreads();

        if (threadIdx.x == 0) {
            double v = dwarp_sums[0];
            #pragma unroll
            for (int w = 1; w < NTHREADS / 32; w++) v += dwarp_sums[w];
            out[0] = (float)(-v * (double)inv_b);
        }
    }
}

extern "C" void kernel_launch(void* const* d_in, const int* in_sizes, int n_in,
                              void* d_out, int out_size)
{
    const float* input  = (const float*)d_in[0];
    const float* target = (const float*)d_in[1];
    float* out = (float*)d_out;

    long long n = (long long)in_sizes[0];   // B * C, divisible by 4
    long long n4 = n >> 2;
    long long B = n / 128;                  // C = 128 for this problem

    cce_fused_kernel<<<NBLOCKS, NTHREADS>>>(input, target, n4, 1.0f / (float)B, out);
}

// round 7
// speedup vs baseline: 1.0510x; 1.0510x over previous
#include <cuda_runtime.h>

#define EPS 1e-8f
#define NTHREADS 256
#define NBLOCKS 1024              // 1024*256*32 = 2^23 float4 = exact bench shape; <=1184 (one wave)
#define FIXED_ITERS 32
#define MAX_PARTIALS 4096

__device__ float g_partials[MAX_PARTIALS];
__device__ unsigned int g_done_count;   // zero-init; reset by last block each launch

__global__ __launch_bounds__(NTHREADS, 8) void cce_fused_kernel(
    const float* __restrict__ input,
    const float* __restrict__ target,
    long long n4,        // number of float4 elements
    float inv_b,
    float* __restrict__ out)
{
    const float4* __restrict__ in4 = (const float4*)input;
    const float4* __restrict__ tg4 = (const float4*)target;

    const long long stride = (long long)NBLOCKS * NTHREADS;
    const long long base = (long long)blockIdx.x * NTHREADS + threadIdx.x;

    float acc0 = 0.0f, acc1 = 0.0f, acc2 = 0.0f, acc3 = 0.0f;

    if (n4 == stride * FIXED_ITERS) {
        // fast path: compile-time trip count, no bounds checks, interleaved stride
        #pragma unroll 4
        for (int it = 0; it < FIXED_ITERS; it++) {
            long long i = base + (long long)it * stride;
            float4 a = __ldcs(&in4[i]);
            float4 t = __ldcs(&tg4[i]);
            acc0 += a.x * __logf(t.x + EPS);
            acc1 += a.y * __logf(t.y + EPS);
            acc2 += a.z * __logf(t.z + EPS);
            acc3 += a.w * __logf(t.w + EPS);
        }
    } else {
        // generic grid-stride fallback
        #pragma unroll 2
        for (long long i = base; i < n4; i += stride) {
            float4 a = __ldcs(&in4[i]);
            float4 t = __ldcs(&tg4[i]);
            acc0 += a.x * __logf(t.x + EPS);
            acc1 += a.y * __logf(t.y + EPS);
            acc2 += a.z * __logf(t.z + EPS);
            acc3 += a.w * __logf(t.w + EPS);
        }
    }

    float acc = (acc0 + acc1) + (acc2 + acc3);

    // intra-block reduction (fp32)
    #pragma unroll
    for (int off = 16; off > 0; off >>= 1)
        acc += __shfl_xor_sync(0xFFFFFFFFu, acc, off);

    __shared__ float warp_sums[NTHREADS / 32];
    int lane = threadIdx.x & 31;
    int wid  = threadIdx.x >> 5;
    if (lane == 0) warp_sums[wid] = acc;
    __syncthreads();

    __shared__ bool is_last;
    if (threadIdx.x == 0) {
        float v = warp_sums[0];
        #pragma unroll
        for (int w = 1; w < NTHREADS / 32; w++) v += warp_sums[w];
        g_partials[blockIdx.x] = v;
        __threadfence();
        unsigned int prev = atomicAdd(&g_done_count, 1u);
        is_last = (prev == (unsigned int)(gridDim.x - 1));
        if (is_last) g_done_count = 0u;   // reset for next graph replay
    }
    __syncthreads();

    if (is_last) {
        // deterministic final sum in double (fixed read + reduction order)
        double dacc = 0.0;
        for (int i = threadIdx.x; i < NBLOCKS; i += NTHREADS)
            dacc += (double)g_partials[i];

        #pragma unroll
        for (int off = 16; off > 0; off >>= 1)
            dacc += __shfl_xor_sync(0xFFFFFFFFu, dacc, off);

        __shared__ double dwarp_sums[NTHREADS / 32];
        if (lane == 0) dwarp_sums[wid] = dacc;
        __syncthreads();

        if (threadIdx.x == 0) {
            double v = dwarp_sums[0];
            #pragma unroll
            for (int w = 1; w < NTHREADS / 32; w++) v += dwarp_sums[w];
            out[0] = (float)(-v * (double)inv_b);
        }
    }
}

extern "C" void kernel_launch(void* const* d_in, const int* in_sizes, int n_in,
                              void* d_out, int out_size)
{
    const float* input  = (const float*)d_in[0];
    const float* target = (const float*)d_in[1];
    float* out = (float*)d_out;

    long long n = (long long)in_sizes[0];   // B * C, divisible by 4
    long long n4 = n >> 2;
    long long B = n / 128;                  // C = 128 for this problem

    cce_fused_kernel<<<NBLOCKS, NTHREADS>>>(input, target, n4, 1.0f / (float)B, out);
}

// round 8
// speedup vs baseline: 1.0569x; 1.0056x over previous
#include <cuda_runtime.h>

#define EPS 1e-8f
#define NTHREADS 256
#define NBLOCKS 512               // 512*256*32 LDG.256-iters * 8 floats = 2^25 = exact bench shape
#define FIXED_ITERS 32
#define MAX_PARTIALS 4096

__device__ float g_partials[MAX_PARTIALS];
__device__ unsigned int g_done_count;   // zero-init; reset by last block each launch

__device__ __forceinline__ void ldg256(const float* p,
    float& v0, float& v1, float& v2, float& v3,
    float& v4, float& v5, float& v6, float& v7)
{
    asm volatile("ld.global.nc.v8.f32 {%0,%1,%2,%3,%4,%5,%6,%7}, [%8];"
        : "=f"(v0), "=f"(v1), "=f"(v2), "=f"(v3),
          "=f"(v4), "=f"(v5), "=f"(v6), "=f"(v7)
        : "l"(p));
}

__global__ __launch_bounds__(NTHREADS) void cce_fused_kernel(
    const float* __restrict__ input,
    const float* __restrict__ target,
    long long n,         // total elements
    float inv_b,
    float* __restrict__ out)
{
    const long long stride = (long long)NBLOCKS * NTHREADS;   // in 32B (8-float) units
    const long long base = (long long)blockIdx.x * NTHREADS + threadIdx.x;
    const long long n8 = n >> 3;

    float acc0 = 0.0f, acc1 = 0.0f, acc2 = 0.0f, acc3 = 0.0f;

    if (n8 == stride * FIXED_ITERS) {
        // fast path: exact compile-time trip count, interleaved stride, 256-bit loads
        #pragma unroll 4
        for (int it = 0; it < FIXED_ITERS; it++) {
            long long i = (base + (long long)it * stride) << 3;
            float a0,a1,a2,a3,a4,a5,a6,a7;
            float t0,t1,t2,t3,t4,t5,t6,t7;
            ldg256(input  + i, a0,a1,a2,a3,a4,a5,a6,a7);
            ldg256(target + i, t0,t1,t2,t3,t4,t5,t6,t7);
            acc0 += a0 * __logf(t0 + EPS);
            acc1 += a1 * __logf(t1 + EPS);
            acc2 += a2 * __logf(t2 + EPS);
            acc3 += a3 * __logf(t3 + EPS);
            acc0 += a4 * __logf(t4 + EPS);
            acc1 += a5 * __logf(t5 + EPS);
            acc2 += a6 * __logf(t6 + EPS);
            acc3 += a7 * __logf(t7 + EPS);
        }
    } else {
        // generic fallback: float4 grid-stride over n4, scalar tail
        const float4* __restrict__ in4 = (const float4*)input;
        const float4* __restrict__ tg4 = (const float4*)target;
        long long n4 = n >> 2;
        for (long long i = base; i < n4; i += stride) {
            float4 a = __ldcs(&in4[i]);
            float4 t = __ldcs(&tg4[i]);
            acc0 += a.x * __logf(t.x + EPS);
            acc1 += a.y * __logf(t.y + EPS);
            acc2 += a.z * __logf(t.z + EPS);
            acc3 += a.w * __logf(t.w + EPS);
        }
        for (long long i = (n4 << 2) + base; i < n; i += stride)
            acc0 += input[i] * __logf(target[i] + EPS);
    }

    float acc = (acc0 + acc1) + (acc2 + acc3);

    // intra-block reduction (fp32)
    #pragma unroll
    for (int off = 16; off > 0; off >>= 1)
        acc += __shfl_xor_sync(0xFFFFFFFFu, acc, off);

    __shared__ float warp_sums[NTHREADS / 32];
    int lane = threadIdx.x & 31;
    int wid  = threadIdx.x >> 5;
    if (lane == 0) warp_sums[wid] = acc;
    __syncthreads();

    __shared__ bool is_last;
    if (threadIdx.x == 0) {
        float v = warp_sums[0];
        #pragma unroll
        for (int w = 1; w < NTHREADS / 32; w++) v += warp_sums[w];
        g_partials[blockIdx.x] = v;
        __threadfence();
        unsigned int prev = atomicAdd(&g_done_count, 1u);
        is_last = (prev == (unsigned int)(gridDim.x - 1));
        if (is_last) g_done_count = 0u;   // reset for next graph replay
    }
    __syncthreads();

    if (is_last) {
        // deterministic final sum in double (fixed read + reduction order)
        double dacc = 0.0;
        for (int i = threadIdx.x; i < NBLOCKS; i += NTHREADS)
            dacc += (double)g_partials[i];

        #pragma unroll
        for (int off = 16; off > 0; off >>= 1)
            dacc += __shfl_xor_sync(0xFFFFFFFFu, dacc, off);

        __shared__ double dwarp_sums[NTHREADS / 32];
        if (lane == 0) dwarp_sums[wid] = dacc;
        __syncthreads();

        if (threadIdx.x == 0) {
            double v = dwarp_sums[0];
            #pragma unroll
            for (int w = 1; w < NTHREADS / 32; w++) v += dwarp_sums[w];
            out[0] = (float)(-v * (double)inv_b);
        }
    }
}

extern "C" void kernel_launch(void* const* d_in, const int* in_sizes, int n_in,
                              void* d_out, int out_size)
{
    const float* input  = (const float*)d_in[0];
    const float* target = (const float*)d_in[1];
    float* out = (float*)d_out;

    long long n = (long long)in_sizes[0];   // B * C
    long long B = n / 128;                  // C = 128 for this problem

    cce_fused_kernel<<<NBLOCKS, NTHREADS>>>(input, target, n, 1.0f / (float)B, out);
}